// round 7
// baseline (speedup 1.0000x reference)
#include <cuda_runtime.h>
#include <cuda_bf16.h>
#include <mma.h>

using namespace nvcuda;

#define N_NODES 100000
#define N_EDGES 1600000
#define DIM 128
#define ODIM 16
#define MLP_CTAS 782            // ceil(100000/128)

// ---------------- static scratch (no allocs allowed) ----------------
__device__ float g_y1[N_NODES * DIM];
__device__ float g_y2[N_NODES * DIM];
__device__ int   g_deg[N_NODES];
__device__ int   g_start[N_NODES];
__device__ int   g_pos[N_NODES];
__device__ float g_dinv[N_NODES];
__device__ int   g_csr[N_EDGES];
__device__ int   g_cursor;
__device__ int   g_shift;   // 0 = int32 edge words, 1 = int64 (read low word)

// ---------------- dtype detect + zero ----------------
__global__ void k_zero(const int* __restrict__ eraw) {
    int i = blockIdx.x * blockDim.x + threadIdx.x;
    if (i < N_NODES) g_deg[i] = 0;
    if (i == 0) {
        g_cursor = 0;
        int is64 = 1;
        for (int e = 0; e < 64; e++) {
            if (eraw[2 * e + 1] != 0) { is64 = 0; break; }
        }
        g_shift = is64;
    }
}

__device__ __forceinline__ int edge_at(const int* __restrict__ eraw, long long pos) {
    return eraw[pos << g_shift];
}

// ---------------- CSR build ----------------
__global__ void k_count(const int* __restrict__ eraw) {
    int e = blockIdx.x * blockDim.x + threadIdx.x;
    if (e < N_EDGES) atomicAdd(&g_deg[edge_at(eraw, e)], 1);
}

__global__ void k_alloc() {
    int i = blockIdx.x * blockDim.x + threadIdx.x;
    if (i < N_NODES) {
        int d = g_deg[i];
        int s = atomicAdd(&g_cursor, d);
        g_start[i] = s;
        g_pos[i]   = s;
        g_dinv[i]  = 1.0f / (float)max(d, 1);
    }
}

__global__ void k_scatter(const int* __restrict__ eraw) {
    int e = blockIdx.x * blockDim.x + threadIdx.x;
    if (e < N_EDGES) {
        int r = edge_at(eraw, e);
        int c = edge_at(eraw, (long long)N_EDGES + e);
        int p = atomicAdd(&g_pos[r], 1);
        g_csr[p] = c;
    }
}

// ---------------- SpMM with 4-way edge ILP ---------------------------------
// one warp per node, float4 per lane; 4 independent gathers in flight.
__global__ void k_spmm(const float4* __restrict__ vin, float4* __restrict__ vout) {
    int node = blockIdx.x * blockDim.y + threadIdx.y;
    if (node >= N_NODES) return;
    int lane = threadIdx.x;
    int s = g_start[node];
    int d = g_deg[node];
    float4 a0 = make_float4(0.f, 0.f, 0.f, 0.f);
    float4 a1 = a0, a2 = a0, a3 = a0;
    int k = 0;
    for (; k + 4 <= d; k += 4) {
        int c0 = __ldg(&g_csr[s + k + 0]);
        int c1 = __ldg(&g_csr[s + k + 1]);
        int c2 = __ldg(&g_csr[s + k + 2]);
        int c3 = __ldg(&g_csr[s + k + 3]);
        float4 v0 = __ldg(&vin[c0 * 32 + lane]);
        float4 v1 = __ldg(&vin[c1 * 32 + lane]);
        float4 v2 = __ldg(&vin[c2 * 32 + lane]);
        float4 v3 = __ldg(&vin[c3 * 32 + lane]);
        a0.x += v0.x; a0.y += v0.y; a0.z += v0.z; a0.w += v0.w;
        a1.x += v1.x; a1.y += v1.y; a1.z += v1.z; a1.w += v1.w;
        a2.x += v2.x; a2.y += v2.y; a2.z += v2.z; a2.w += v2.w;
        a3.x += v3.x; a3.y += v3.y; a3.z += v3.z; a3.w += v3.w;
    }
    for (; k < d; k++) {
        int c = __ldg(&g_csr[s + k]);
        float4 v = __ldg(&vin[c * 32 + lane]);
        a0.x += v.x; a0.y += v.y; a0.z += v.z; a0.w += v.w;
    }
    a0.x += a1.x + a2.x + a3.x;
    a0.y += a1.y + a2.y + a3.y;
    a0.z += a1.z + a2.z + a3.z;
    a0.w += a1.w + a2.w + a3.w;
    vout[node * 32 + lane] = a0;
}

// ---------------- MLP tile: tf32 WMMA stage1 + tf32 WMMA stage2 ------------
// smem S [128][132]: A tile during K loop, reused row-major H afterwards.
#define LDS_T 132
#define SM_S     0                              // 128*132*4 = 67584
#define SM_WCS   67584                          // 128*16*4  = 8192
#define SM_O     75776                          // 128*16*4  = 8192
#define SM_BIAS  83968                          // 128*4
#define SM_DSC   84480                          // 128*4
#define SM_TOTAL 84992

template <int SCALE_MODE, bool FIRST>
__device__ __forceinline__ void mlp_tile(
    int m0, const float* __restrict__ A, const float* __restrict__ W,
    const float* __restrict__ bias, const float* __restrict__ Wc_br,
    const float* __restrict__ bc, float* __restrict__ out, char* smem_raw) {

    float* S      = (float*)(smem_raw + SM_S);
    float* Wcs    = (float*)(smem_raw + SM_WCS);   // [128][16]
    float* O      = (float*)(smem_raw + SM_O);     // [128][16]
    float* bias_s = (float*)(smem_raw + SM_BIAS);
    float* dsc    = (float*)(smem_raw + SM_DSC);

    const int tid = threadIdx.x;
    const int wid = tid >> 5;
    const int mrow0 = (wid & 3) * 32;     // stage1 M split (4 warps)
    const int ncol0 = (wid >> 2) * 64;    // stage1 N split (2 warps)
    const int mrow2 = wid * 16;           // stage2 M split (8 warps)

    // constants into smem (Wc slice pre-converted to tf32 for stage2)
    #pragma unroll
    for (int p = 0; p < 2; p++) {
        int t = tid + 256 * p;
        float4 v = __ldg(&((const float4*)Wc_br)[t]);
        v.x = wmma::__float_to_tf32(v.x);
        v.y = wmma::__float_to_tf32(v.y);
        v.z = wmma::__float_to_tf32(v.z);
        v.w = wmma::__float_to_tf32(v.w);
        ((float4*)Wcs)[t] = v;
    }
    if (tid < 128) {
        bias_s[tid] = __ldg(&bias[tid]);
        if (SCALE_MODE == 0) dsc[tid] = 1.f;
        else {
            int m = m0 + tid;
            float di = (m < N_NODES) ? g_dinv[m] : 1.f;
            dsc[tid] = (SCALE_MODE == 1) ? di : di * di;
        }
    }

    // stage A tile into smem
    {
        int m    = tid >> 1;
        int half = (tid & 1) * 64;
        bool ok  = (m0 + m) < N_NODES;
        const float4* src = (const float4*)&A[(size_t)(m0 + m) * 128 + half];
        float4* dst = (float4*)&S[m * LDS_T + half];
        #pragma unroll
        for (int q = 0; q < 16; q++) {
            float4 v = ok ? __ldg(&src[q]) : make_float4(0.f, 0.f, 0.f, 0.f);
            dst[q] = v;
        }
    }
    __syncthreads();

    // ---- stage1: H(pre) = A @ W, each warp 32x64 ----
    wmma::fragment<wmma::accumulator, 16, 16, 8, float> acc[2][4];
    #pragma unroll
    for (int i = 0; i < 2; i++)
        #pragma unroll
        for (int j = 0; j < 4; j++) wmma::fill_fragment(acc[i][j], 0.f);

    #pragma unroll 4
    for (int k0 = 0; k0 < 128; k0 += 8) {
        wmma::fragment<wmma::matrix_a, 16, 16, 8, wmma::precision::tf32,
                       wmma::row_major> af[2];
        #pragma unroll
        for (int i = 0; i < 2; i++) {
            wmma::load_matrix_sync(af[i], S + (mrow0 + i * 16) * LDS_T + k0, LDS_T);
            #pragma unroll
            for (int e = 0; e < af[i].num_elements; e++)
                af[i].x[e] = wmma::__float_to_tf32(af[i].x[e]);
        }
        wmma::fragment<wmma::matrix_b, 16, 16, 8, wmma::precision::tf32,
                       wmma::row_major> bf[4];
        #pragma unroll
        for (int j = 0; j < 4; j++) {
            wmma::load_matrix_sync(bf[j], W + k0 * 128 + ncol0 + j * 16, 128);
            #pragma unroll
            for (int e = 0; e < bf[j].num_elements; e++)
                bf[j].x[e] = wmma::__float_to_tf32(bf[j].x[e]);
        }
        #pragma unroll
        for (int i = 0; i < 2; i++)
            #pragma unroll
            for (int j = 0; j < 4; j++)
                wmma::mma_sync(acc[i][j], af[i], bf[j], acc[i][j]);
    }
    __syncthreads();   // done reading S as A

    // store pre-activation ROW-major into S as H[m][c]
    #pragma unroll
    for (int i = 0; i < 2; i++)
        #pragma unroll
        for (int j = 0; j < 4; j++)
            wmma::store_matrix_sync(S + (mrow0 + i * 16) * LDS_T + ncol0 + j * 16,
                                    acc[i][j], LDS_T, wmma::mem_row_major);
    __syncthreads();

    // fixup in row-major: h[m][c] = relu(v * dsc[m] + bias[c]), also tf32-round
    {
        int m  = tid >> 1;
        int ch = (tid & 1) * 64;
        float dm = dsc[m];
        #pragma unroll
        for (int q = 0; q < 16; q++) {
            int c = ch + q * 4;
            float4 v  = *(float4*)&S[m * LDS_T + c];
            float4 bb = *(const float4*)&bias_s[c];
            v.x = wmma::__float_to_tf32(fmaxf(fmaf(v.x, dm, bb.x), 0.f));
            v.y = wmma::__float_to_tf32(fmaxf(fmaf(v.y, dm, bb.y), 0.f));
            v.z = wmma::__float_to_tf32(fmaxf(fmaf(v.z, dm, bb.z), 0.f));
            v.w = wmma::__float_to_tf32(fmaxf(fmaf(v.w, dm, bb.w), 0.f));
            *(float4*)&S[m * LDS_T + c] = v;
        }
    }
    __syncthreads();

    // ---- stage2: O = H @ Wc (128x16), each warp 16 rows ----
    {
        wmma::fragment<wmma::accumulator, 16, 16, 8, float> acc2;
        wmma::fill_fragment(acc2, 0.f);
        #pragma unroll
        for (int k0 = 0; k0 < 128; k0 += 8) {
            wmma::fragment<wmma::matrix_a, 16, 16, 8, wmma::precision::tf32,
                           wmma::row_major> af2;
            wmma::load_matrix_sync(af2, S + mrow2 * LDS_T + k0, LDS_T);
            wmma::fragment<wmma::matrix_b, 16, 16, 8, wmma::precision::tf32,
                           wmma::row_major> bf2;
            wmma::load_matrix_sync(bf2, Wcs + k0 * 16, 16);
            wmma::mma_sync(acc2, af2, bf2, acc2);
        }
        wmma::store_matrix_sync(O + mrow2 * 16, acc2, 16, wmma::mem_row_major);
    }
    __syncthreads();

    // global write/accumulate: 2048 floats, 8 per thread
    {
        int m  = tid >> 1;
        int c0 = (tid & 1) * 8;
        int node = m0 + m;
        if (node < N_NODES) {
            float4 v0 = *(const float4*)&O[m * 16 + c0];
            float4 v1 = *(const float4*)&O[m * 16 + c0 + 4];
            float* dst = &out[node * 16 + c0];
            if (FIRST) {
                float4 bc0 = *(const float4*)&bc[c0];
                float4 bc1 = *(const float4*)&bc[c0 + 4];
                v0.x += bc0.x; v0.y += bc0.y; v0.z += bc0.z; v0.w += bc0.w;
                v1.x += bc1.x; v1.y += bc1.y; v1.z += bc1.z; v1.w += bc1.w;
                *(float4*)&dst[0] = v0;
                *(float4*)&dst[4] = v1;
            } else {
                float4 o0 = *(const float4*)&dst[0];
                float4 o1 = *(const float4*)&dst[4];
                o0.x += v0.x; o0.y += v0.y; o0.z += v0.z; o0.w += v0.w;
                o1.x += v1.x; o1.y += v1.y; o1.z += v1.z; o1.w += v1.w;
                *(float4*)&dst[0] = o0;
                *(float4*)&dst[4] = o1;
            }
        }
    }
}

__global__ __launch_bounds__(256, 2)
void k_mlp_ego(const float* __restrict__ x,
               const float* __restrict__ W, const float* __restrict__ b,
               const float* __restrict__ Wc, const float* __restrict__ bc,
               float* __restrict__ out) {
    extern __shared__ char smem_raw[];
    mlp_tile<0, true>(blockIdx.x * 128, x, W, b, Wc, bc, out, smem_raw);
}

__global__ __launch_bounds__(256, 2)
void k_mlp_b1(const float* __restrict__ y1f,
              const float* __restrict__ W, const float* __restrict__ b,
              const float* __restrict__ Wc, float* __restrict__ out) {
    extern __shared__ char smem_raw[];
    mlp_tile<1, false>(blockIdx.x * 128, y1f, W, b, Wc + 2048, nullptr, out, smem_raw);
}

__global__ __launch_bounds__(256, 2)
void k_mlp_b2(const float* __restrict__ y2f,
              const float* __restrict__ W, const float* __restrict__ b,
              const float* __restrict__ Wc, float* __restrict__ out) {
    extern __shared__ char smem_raw[];
    mlp_tile<2, false>(blockIdx.x * 128, y2f, W, b, Wc + 4096, nullptr, out, smem_raw);
}

// ---------------- launch: fork/join multi-stream for overlap ----------------
extern "C" void kernel_launch(void* const* d_in, const int* in_sizes, int n_in,
                              void* d_out, int out_size) {
    const float* x    = (const float*)d_in[0];
    const int*   ei   = (const int*)d_in[1];
    const float* Wego = (const float*)d_in[2];
    const float* bego = (const float*)d_in[3];
    const float* W1   = (const float*)d_in[4];
    const float* b1   = (const float*)d_in[5];
    const float* W2   = (const float*)d_in[6];
    const float* b2   = (const float*)d_in[7];
    const float* Wc   = (const float*)d_in[8];
    const float* bc   = (const float*)d_in[9];
    float*       out  = (float*)d_out;

    void *py1 = nullptr, *py2 = nullptr;
    cudaGetSymbolAddress(&py1, g_y1);
    cudaGetSymbolAddress(&py2, g_y2);

    cudaFuncSetAttribute(k_mlp_ego, cudaFuncAttributeMaxDynamicSharedMemorySize, SM_TOTAL);
    cudaFuncSetAttribute(k_mlp_b1,  cudaFuncAttributeMaxDynamicSharedMemorySize, SM_TOTAL);
    cudaFuncSetAttribute(k_mlp_b2,  cudaFuncAttributeMaxDynamicSharedMemorySize, SM_TOTAL);

    cudaStream_t sB;
    cudaStreamCreateWithFlags(&sB, cudaStreamNonBlocking);
    cudaEvent_t eFork, eS1, eS2, eJoin;
    cudaEventCreateWithFlags(&eFork, cudaEventDisableTiming);
    cudaEventCreateWithFlags(&eS1,   cudaEventDisableTiming);
    cudaEventCreateWithFlags(&eS2,   cudaEventDisableTiming);
    cudaEventCreateWithFlags(&eJoin, cudaEventDisableTiming);

    cudaEventRecord(eFork, 0);
    cudaStreamWaitEvent(sB, eFork, 0);

    // stream B: ego branch — depends only on x
    k_mlp_ego<<<MLP_CTAS, 256, SM_TOTAL, sB>>>(x, Wego, bego, Wc, bc, out);

    // stream 0: CSR build + spmm1 + spmm2
    k_zero<<<(N_NODES + 1023) / 1024, 1024>>>(ei);
    k_count<<<(N_EDGES + 255) / 256, 256>>>(ei);
    k_alloc<<<(N_NODES + 255) / 256, 256>>>();
    k_scatter<<<(N_EDGES + 255) / 256, 256>>>(ei);

    dim3 sb(32, 4);
    k_spmm<<<(N_NODES + 3) / 4, sb>>>((const float4*)x, (float4*)py1);
    cudaEventRecord(eS1, 0);
    k_spmm<<<(N_NODES + 3) / 4, sb>>>((const float4*)py1, (float4*)py2);
    cudaEventRecord(eS2, 0);

    // stream B: branch 1 after spmm1 (overlaps spmm2), branch 2 after spmm2
    cudaStreamWaitEvent(sB, eS1, 0);
    k_mlp_b1<<<MLP_CTAS, 256, SM_TOTAL, sB>>>((const float*)py1, W1, b1, Wc, out);
    cudaStreamWaitEvent(sB, eS2, 0);
    k_mlp_b2<<<MLP_CTAS, 256, SM_TOTAL, sB>>>((const float*)py2, W2, b2, Wc, out);

    cudaEventRecord(eJoin, sB);
    cudaStreamWaitEvent(0, eJoin, 0);

    cudaEventDestroy(eFork);
    cudaEventDestroy(eS1);
    cudaEventDestroy(eS2);
    cudaEventDestroy(eJoin);
}

// round 8
// speedup vs baseline: 1.0805x; 1.0805x over previous
#include <cuda_runtime.h>
#include <cuda_bf16.h>
#include <mma.h>

using namespace nvcuda;

#define N_NODES 100000
#define N_EDGES 1600000
#define DIM 128
#define ODIM 16
#define MLP_CTAS 782            // ceil(100000/128)

// ---------------- static scratch (no allocs allowed) ----------------
__device__ float g_y1[N_NODES * DIM];
__device__ float g_y2[N_NODES * DIM];
__device__ int   g_deg[N_NODES];
__device__ int   g_start[N_NODES];
__device__ int   g_pos[N_NODES];
__device__ float g_dinv[N_NODES];
__device__ int   g_csr[N_EDGES];
__device__ int   g_cursor;
__device__ int   g_shift;   // 0 = int32 edge words, 1 = int64 (read low word)

// ---------------- dtype detect + zero ----------------
__global__ void k_zero(const int* __restrict__ eraw) {
    int i = blockIdx.x * blockDim.x + threadIdx.x;
    if (i < N_NODES) g_deg[i] = 0;
    if (i == 0) {
        g_cursor = 0;
        int is64 = 1;
        for (int e = 0; e < 64; e++) {
            if (eraw[2 * e + 1] != 0) { is64 = 0; break; }
        }
        g_shift = is64;
    }
}

__device__ __forceinline__ int edge_at(const int* __restrict__ eraw, long long pos) {
    return eraw[pos << g_shift];
}

// ---------------- CSR build ----------------
__global__ void k_count(const int* __restrict__ eraw) {
    int e = blockIdx.x * blockDim.x + threadIdx.x;
    if (e < N_EDGES) atomicAdd(&g_deg[edge_at(eraw, e)], 1);
}

__global__ void k_alloc() {
    int i = blockIdx.x * blockDim.x + threadIdx.x;
    if (i < N_NODES) {
        int d = g_deg[i];
        int s = atomicAdd(&g_cursor, d);
        g_start[i] = s;
        g_pos[i]   = s;
        g_dinv[i]  = 1.0f / (float)max(d, 1);
    }
}

__global__ void k_scatter(const int* __restrict__ eraw) {
    int e = blockIdx.x * blockDim.x + threadIdx.x;
    if (e < N_EDGES) {
        int r = edge_at(eraw, e);
        int c = edge_at(eraw, (long long)N_EDGES + e);
        int p = atomicAdd(&g_pos[r], 1);
        g_csr[p] = c;
    }
}

// ---------------- SpMM: y[i,:] = sum_{j in adj(i)} v[j,:] ----------------
__global__ void k_spmm(const float4* __restrict__ vin, float4* __restrict__ vout) {
    int node = blockIdx.x * blockDim.y + threadIdx.y;
    if (node >= N_NODES) return;
    int lane = threadIdx.x;
    int s = g_start[node];
    int d = g_deg[node];
    float4 acc = make_float4(0.f, 0.f, 0.f, 0.f);
    int c = (d > 0) ? __ldg(&g_csr[s]) : 0;
    #pragma unroll 2
    for (int k = 0; k < d; k++) {
        int cn = (k + 1 < d) ? __ldg(&g_csr[s + k + 1]) : 0;
        float4 v = __ldg(&vin[c * 32 + lane]);
        acc.x += v.x; acc.y += v.y; acc.z += v.z; acc.w += v.w;
        c = cn;
    }
    vout[node * 32 + lane] = acc;
}

// ---------------- MLP tile (one branch): tf32 WMMA stage1 + classifier ----
// smem S [128][132]: A tile during K loop, reused as Ht[n][m] for stage2.
#define LDS_T 132
#define SM_S     0                              // 128*132*4 = 67584
#define SM_WCS   67584                          // 2048*4
#define SM_BIAS  75776                          // 128*4
#define SM_DSC   76288                          // 128*4
#define SM_TOTAL 76800

template <int SCALE_MODE, bool FIRST>
__device__ __forceinline__ void mlp_tile(
    int m0, const float* __restrict__ A, const float* __restrict__ W,
    const float* __restrict__ bias, const float* __restrict__ Wc_br,
    const float* __restrict__ bc, float* __restrict__ out, char* smem_raw) {

    float* S      = (float*)(smem_raw + SM_S);
    float* Wcs    = (float*)(smem_raw + SM_WCS);
    float* bias_s = (float*)(smem_raw + SM_BIAS);
    float* dsc    = (float*)(smem_raw + SM_DSC);

    const int tid = threadIdx.x;
    const int wid = tid >> 5;
    const int mrow0 = (wid & 1) * 64;     // 2 M groups of 64
    const int ncol0 = (wid >> 1) * 32;    // 4 N groups of 32
    const int oc = tid & 15;
    const int nb = (tid >> 4) * 8;

    #pragma unroll
    for (int p = 0; p < 2; p++) {
        int t = tid + 256 * p;
        ((float4*)Wcs)[t] = __ldg(&((const float4*)Wc_br)[t]);
    }
    if (tid < 128) {
        bias_s[tid] = __ldg(&bias[tid]);
        if (SCALE_MODE == 0) dsc[tid] = 1.f;
        else {
            int m = m0 + tid;
            float di = (m < N_NODES) ? g_dinv[m] : 1.f;
            dsc[tid] = (SCALE_MODE == 1) ? di : di * di;
        }
    }

    // stage A tile into smem (streaming loads: keep L1 for W fragments)
    {
        int m    = tid >> 1;
        int half = (tid & 1) * 64;
        bool ok  = (m0 + m) < N_NODES;
        const float4* src = (const float4*)&A[(size_t)(m0 + m) * 128 + half];
        float4* dst = (float4*)&S[m * LDS_T + half];
        #pragma unroll
        for (int q = 0; q < 16; q++) {
            float4 v = ok ? __ldcs(&src[q]) : make_float4(0.f, 0.f, 0.f, 0.f);
            dst[q] = v;
        }
    }
    __syncthreads();

    // ---- stage1: each warp 64Mx32N; B frag loads halved vs 32x64 ----
    wmma::fragment<wmma::accumulator, 16, 16, 8, float> acc[4][2];
    #pragma unroll
    for (int i = 0; i < 4; i++)
        #pragma unroll
        for (int j = 0; j < 2; j++) wmma::fill_fragment(acc[i][j], 0.f);

    #pragma unroll 4
    for (int k0 = 0; k0 < 128; k0 += 8) {
        wmma::fragment<wmma::matrix_b, 16, 16, 8, wmma::precision::tf32,
                       wmma::row_major> bf[2];
        #pragma unroll
        for (int j = 0; j < 2; j++) {
            wmma::load_matrix_sync(bf[j], W + k0 * 128 + ncol0 + j * 16, 128);
            #pragma unroll
            for (int e = 0; e < bf[j].num_elements; e++)
                bf[j].x[e] = wmma::__float_to_tf32(bf[j].x[e]);
        }
        wmma::fragment<wmma::matrix_a, 16, 16, 8, wmma::precision::tf32,
                       wmma::row_major> af;
        #pragma unroll
        for (int i = 0; i < 4; i++) {
            wmma::load_matrix_sync(af, S + (mrow0 + i * 16) * LDS_T + k0, LDS_T);
            #pragma unroll
            for (int e = 0; e < af.num_elements; e++)
                af.x[e] = wmma::__float_to_tf32(af.x[e]);
            #pragma unroll
            for (int j = 0; j < 2; j++)
                wmma::mma_sync(acc[i][j], af, bf[j], acc[i][j]);
        }
    }
    __syncthreads();

    // store acc col-major into S as Ht[n][m]
    #pragma unroll
    for (int i = 0; i < 4; i++)
        #pragma unroll
        for (int j = 0; j < 2; j++)
            wmma::store_matrix_sync(S + (ncol0 + j * 16) * LDS_T + (mrow0 + i * 16),
                                    acc[i][j], LDS_T, wmma::mem_col_major);
    __syncthreads();

    // fixup: h = relu(acc * dsc[m] + bias[c]) in place
    {
        int c  = tid >> 1;
        int mh = (tid & 1) * 64;
        float bb = bias_s[c];
        #pragma unroll
        for (int q = 0; q < 16; q++) {
            int m = mh + q * 4;
            float4 v  = *(float4*)&S[c * LDS_T + m];
            float4 dv = *(const float4*)&dsc[m];
            v.x = fmaxf(fmaf(v.x, dv.x, bb), 0.f);
            v.y = fmaxf(fmaf(v.y, dv.y, bb), 0.f);
            v.z = fmaxf(fmaf(v.z, dv.z, bb), 0.f);
            v.w = fmaxf(fmaf(v.w, dv.w, bb), 0.f);
            *(float4*)&S[c * LDS_T + m] = v;
        }
    }
    __syncthreads();

    float oacc[8];
    #pragma unroll
    for (int i = 0; i < 8; i++) oacc[i] = 0.f;
    #pragma unroll 8
    for (int c = 0; c < 128; c++) {
        float w = Wcs[c * 16 + oc];
        float4 h0 = *(const float4*)&S[c * LDS_T + nb];
        float4 h1 = *(const float4*)&S[c * LDS_T + nb + 4];
        oacc[0] += h0.x * w; oacc[1] += h0.y * w;
        oacc[2] += h0.z * w; oacc[3] += h0.w * w;
        oacc[4] += h1.x * w; oacc[5] += h1.y * w;
        oacc[6] += h1.z * w; oacc[7] += h1.w * w;
    }

    if (FIRST) {
        float bcv = __ldg(&bc[oc]);
        #pragma unroll
        for (int i = 0; i < 8; i++) {
            int node = m0 + nb + i;
            if (node < N_NODES) out[node * 16 + oc] = oacc[i] + bcv;
        }
    } else {
        #pragma unroll
        for (int i = 0; i < 8; i++) {
            int node = m0 + nb + i;
            if (node < N_NODES) out[node * 16 + oc] += oacc[i];
        }
    }
}

__global__ __launch_bounds__(256, 2)
void k_mlp_ego(const float* __restrict__ x,
               const float* __restrict__ W, const float* __restrict__ b,
               const float* __restrict__ Wc, const float* __restrict__ bc,
               float* __restrict__ out) {
    extern __shared__ char smem_raw[];
    mlp_tile<0, true>(blockIdx.x * 128, x, W, b, Wc, bc, out, smem_raw);
}

__global__ __launch_bounds__(256, 2)
void k_mlp_b1(const float* __restrict__ y1f,
              const float* __restrict__ W, const float* __restrict__ b,
              const float* __restrict__ Wc, float* __restrict__ out) {
    extern __shared__ char smem_raw[];
    mlp_tile<1, false>(blockIdx.x * 128, y1f, W, b, Wc + 2048, nullptr, out, smem_raw);
}

__global__ __launch_bounds__(256, 2)
void k_mlp_b2(const float* __restrict__ y2f,
              const float* __restrict__ W, const float* __restrict__ b,
              const float* __restrict__ Wc, float* __restrict__ out) {
    extern __shared__ char smem_raw[];
    mlp_tile<2, false>(blockIdx.x * 128, y2f, W, b, Wc + 4096, nullptr, out, smem_raw);
}

// ---------------- launch: fork/join multi-stream for overlap ----------------
// NOTE: ego is deliberately the 4th host-side launch — the bench's ncu capture
// profiles the 4th launch, giving us MLP pipe data next round.
extern "C" void kernel_launch(void* const* d_in, const int* in_sizes, int n_in,
                              void* d_out, int out_size) {
    const float* x    = (const float*)d_in[0];
    const int*   ei   = (const int*)d_in[1];
    const float* Wego = (const float*)d_in[2];
    const float* bego = (const float*)d_in[3];
    const float* W1   = (const float*)d_in[4];
    const float* b1   = (const float*)d_in[5];
    const float* W2   = (const float*)d_in[6];
    const float* b2   = (const float*)d_in[7];
    const float* Wc   = (const float*)d_in[8];
    const float* bc   = (const float*)d_in[9];
    float*       out  = (float*)d_out;

    void *py1 = nullptr, *py2 = nullptr;
    cudaGetSymbolAddress(&py1, g_y1);
    cudaGetSymbolAddress(&py2, g_y2);

    cudaFuncSetAttribute(k_mlp_ego, cudaFuncAttributeMaxDynamicSharedMemorySize, SM_TOTAL);
    cudaFuncSetAttribute(k_mlp_b1,  cudaFuncAttributeMaxDynamicSharedMemorySize, SM_TOTAL);
    cudaFuncSetAttribute(k_mlp_b2,  cudaFuncAttributeMaxDynamicSharedMemorySize, SM_TOTAL);

    cudaStream_t sB;
    cudaStreamCreateWithFlags(&sB, cudaStreamNonBlocking);
    cudaEvent_t eFork, eS1, eS2, eJoin;
    cudaEventCreateWithFlags(&eFork, cudaEventDisableTiming);
    cudaEventCreateWithFlags(&eS1,   cudaEventDisableTiming);
    cudaEventCreateWithFlags(&eS2,   cudaEventDisableTiming);
    cudaEventCreateWithFlags(&eJoin, cudaEventDisableTiming);

    // stream 0: CSR build head (launches 1-3)
    k_zero<<<(N_NODES + 1023) / 1024, 1024>>>(ei);
    k_count<<<(N_EDGES + 255) / 256, 256>>>(ei);
    k_alloc<<<(N_NODES + 255) / 256, 256>>>();

    // fork + ego as the 4th launch (profiled)
    cudaEventRecord(eFork, 0);
    cudaStreamWaitEvent(sB, eFork, 0);
    k_mlp_ego<<<MLP_CTAS, 256, SM_TOTAL, sB>>>(x, Wego, bego, Wc, bc, out);

    // stream 0: rest of CSR + spmm chain
    k_scatter<<<(N_EDGES + 255) / 256, 256>>>(ei);
    dim3 sb(32, 4);
    k_spmm<<<(N_NODES + 3) / 4, sb>>>((const float4*)x, (float4*)py1);
    cudaEventRecord(eS1, 0);
    k_spmm<<<(N_NODES + 3) / 4, sb>>>((const float4*)py1, (float4*)py2);
    cudaEventRecord(eS2, 0);

    // stream B: branch 1 after spmm1 (overlaps spmm2), branch 2 after spmm2
    cudaStreamWaitEvent(sB, eS1, 0);
    k_mlp_b1<<<MLP_CTAS, 256, SM_TOTAL, sB>>>((const float*)py1, W1, b1, Wc, out);
    cudaStreamWaitEvent(sB, eS2, 0);
    k_mlp_b2<<<MLP_CTAS, 256, SM_TOTAL, sB>>>((const float*)py2, W2, b2, Wc, out);

    cudaEventRecord(eJoin, sB);
    cudaStreamWaitEvent(0, eJoin, 0);

    cudaEventDestroy(eFork);
    cudaEventDestroy(eS1);
    cudaEventDestroy(eS2);
    cudaEventDestroy(eJoin);
}

// round 9
// speedup vs baseline: 1.1465x; 1.0610x over previous
#include <cuda_runtime.h>
#include <cuda_bf16.h>
#include <mma.h>

using namespace nvcuda;

#define N_NODES 100000
#define N_EDGES 1600000
#define DIM 128
#define ODIM 16
#define MLP_CTAS 782            // ceil(100000/128)

// ---------------- static scratch (no allocs allowed) ----------------
__device__ float g_y1[N_NODES * DIM];
__device__ float g_y2[N_NODES * DIM];
__device__ int   g_deg[N_NODES];
__device__ int   g_start[N_NODES];
__device__ int   g_pos[N_NODES];
__device__ float g_dinv[N_NODES];
__device__ int   g_csr[N_EDGES];
__device__ int   g_cursor;
__device__ int   g_shift;   // 0 = int32 edge words, 1 = int64 (read low word)

// ---------------- dtype detect + zero ----------------
__global__ void k_zero(const int* __restrict__ eraw) {
    int i = blockIdx.x * blockDim.x + threadIdx.x;
    if (i < N_NODES) g_deg[i] = 0;
    if (i == 0) {
        g_cursor = 0;
        int is64 = 1;
        for (int e = 0; e < 64; e++) {
            if (eraw[2 * e + 1] != 0) { is64 = 0; break; }
        }
        g_shift = is64;
    }
}

__device__ __forceinline__ int edge_at(const int* __restrict__ eraw, long long pos) {
    return eraw[pos << g_shift];
}

// ---------------- CSR build ----------------
__global__ void k_count(const int* __restrict__ eraw) {
    int e = blockIdx.x * blockDim.x + threadIdx.x;
    if (e < N_EDGES) atomicAdd(&g_deg[edge_at(eraw, e)], 1);
}

__global__ void k_alloc() {
    int i = blockIdx.x * blockDim.x + threadIdx.x;
    if (i < N_NODES) {
        int d = g_deg[i];
        int s = atomicAdd(&g_cursor, d);
        g_start[i] = s;
        g_pos[i]   = s;
        g_dinv[i]  = 1.0f / (float)max(d, 1);
    }
}

__global__ void k_scatter(const int* __restrict__ eraw) {
    int e = blockIdx.x * blockDim.x + threadIdx.x;
    if (e < N_EDGES) {
        int r = edge_at(eraw, e);
        int c = edge_at(eraw, (long long)N_EDGES + e);
        int p = atomicAdd(&g_pos[r], 1);
        g_csr[p] = c;
    }
}

// ---------------- SpMM: y[i,:] = sum_{j in adj(i)} v[j,:] ----------------
__global__ void k_spmm(const float4* __restrict__ vin, float4* __restrict__ vout) {
    int node = blockIdx.x * blockDim.y + threadIdx.y;
    if (node >= N_NODES) return;
    int lane = threadIdx.x;
    int s = g_start[node];
    int d = g_deg[node];
    float4 acc = make_float4(0.f, 0.f, 0.f, 0.f);
    int c = (d > 0) ? __ldg(&g_csr[s]) : 0;
    #pragma unroll 2
    for (int k = 0; k < d; k++) {
        int cn = (k + 1 < d) ? __ldg(&g_csr[s + k + 1]) : 0;
        float4 v = __ldg(&vin[c * 32 + lane]);
        acc.x += v.x; acc.y += v.y; acc.z += v.z; acc.w += v.w;
        c = cn;
    }
    vout[node * 32 + lane] = acc;
}

// ---------------- MLP tile: tf32 WMMA stage1 + tf32 WMMA stage2 ------------
// smem S [128][132]: A tile during K loop, reused ROW-major H afterwards.
#define LDS_T 132
#define SM_S     0                              // 128*132*4 = 67584
#define SM_WCS   67584                          // 128*16*4  = 8192 (tf32-rounded)
#define SM_O     75776                          // 128*16*4  = 8192
#define SM_BIAS  83968                          // 128*4
#define SM_DSC   84480                          // 128*4
#define SM_TOTAL 84992

template <int SCALE_MODE, bool FIRST>
__device__ __forceinline__ void mlp_tile(
    int m0, const float* __restrict__ A, const float* __restrict__ W,
    const float* __restrict__ bias, const float* __restrict__ Wc_br,
    const float* __restrict__ bc, float* __restrict__ out, char* smem_raw) {

    float* S      = (float*)(smem_raw + SM_S);
    float* Wcs    = (float*)(smem_raw + SM_WCS);   // [128][16] tf32
    float* O      = (float*)(smem_raw + SM_O);     // [128][16]
    float* bias_s = (float*)(smem_raw + SM_BIAS);
    float* dsc    = (float*)(smem_raw + SM_DSC);

    const int tid = threadIdx.x;
    const int wid = tid >> 5;
    const int mrow0 = (wid & 1) * 64;     // stage1: 2 M groups of 64
    const int ncol0 = (wid >> 1) * 32;    // stage1: 4 N groups of 32
    const int mrow2 = wid * 16;           // stage2: 8 warps x 16 rows

    // constants (Wc slice pre-rounded to tf32 for stage2)
    #pragma unroll
    for (int p = 0; p < 2; p++) {
        int t = tid + 256 * p;
        float4 v = __ldg(&((const float4*)Wc_br)[t]);
        v.x = wmma::__float_to_tf32(v.x);
        v.y = wmma::__float_to_tf32(v.y);
        v.z = wmma::__float_to_tf32(v.z);
        v.w = wmma::__float_to_tf32(v.w);
        ((float4*)Wcs)[t] = v;
    }
    if (tid < 128) {
        bias_s[tid] = __ldg(&bias[tid]);
        if (SCALE_MODE == 0) dsc[tid] = 1.f;
        else {
            int m = m0 + tid;
            float di = (m < N_NODES) ? g_dinv[m] : 1.f;
            dsc[tid] = (SCALE_MODE == 1) ? di : di * di;
        }
    }

    // stage A tile into smem (streaming loads: keep L1 for W fragments)
    {
        int m    = tid >> 1;
        int half = (tid & 1) * 64;
        bool ok  = (m0 + m) < N_NODES;
        const float4* src = (const float4*)&A[(size_t)(m0 + m) * 128 + half];
        float4* dst = (float4*)&S[m * LDS_T + half];
        #pragma unroll
        for (int q = 0; q < 16; q++) {
            float4 v = ok ? __ldcs(&src[q]) : make_float4(0.f, 0.f, 0.f, 0.f);
            dst[q] = v;
        }
    }
    __syncthreads();

    // ---- stage1: each warp 64Mx32N ----
    wmma::fragment<wmma::accumulator, 16, 16, 8, float> acc[4][2];
    #pragma unroll
    for (int i = 0; i < 4; i++)
        #pragma unroll
        for (int j = 0; j < 2; j++) wmma::fill_fragment(acc[i][j], 0.f);

    #pragma unroll 4
    for (int k0 = 0; k0 < 128; k0 += 8) {
        wmma::fragment<wmma::matrix_b, 16, 16, 8, wmma::precision::tf32,
                       wmma::row_major> bf[2];
        #pragma unroll
        for (int j = 0; j < 2; j++) {
            wmma::load_matrix_sync(bf[j], W + k0 * 128 + ncol0 + j * 16, 128);
            #pragma unroll
            for (int e = 0; e < bf[j].num_elements; e++)
                bf[j].x[e] = wmma::__float_to_tf32(bf[j].x[e]);
        }
        wmma::fragment<wmma::matrix_a, 16, 16, 8, wmma::precision::tf32,
                       wmma::row_major> af;
        #pragma unroll
        for (int i = 0; i < 4; i++) {
            wmma::load_matrix_sync(af, S + (mrow0 + i * 16) * LDS_T + k0, LDS_T);
            #pragma unroll
            for (int e = 0; e < af.num_elements; e++)
                af.x[e] = wmma::__float_to_tf32(af.x[e]);
            #pragma unroll
            for (int j = 0; j < 2; j++)
                wmma::mma_sync(acc[i][j], af, bf[j], acc[i][j]);
        }
    }
    __syncthreads();   // done reading S as A

    // store pre-activation ROW-major into S as H[m][c]
    #pragma unroll
    for (int i = 0; i < 4; i++)
        #pragma unroll
        for (int j = 0; j < 2; j++)
            wmma::store_matrix_sync(S + (mrow0 + i * 16) * LDS_T + ncol0 + j * 16,
                                    acc[i][j], LDS_T, wmma::mem_row_major);
    __syncthreads();

    // fixup row-major: h[m][c] = relu(v * dsc[m] + bias[c]), tf32-rounded
    {
        int m  = tid >> 1;
        int ch = (tid & 1) * 64;
        float dm = dsc[m];
        #pragma unroll
        for (int q = 0; q < 16; q++) {
            int c = ch + q * 4;
            float4 v  = *(float4*)&S[m * LDS_T + c];
            float4 bb = *(const float4*)&bias_s[c];
            v.x = wmma::__float_to_tf32(fmaxf(fmaf(v.x, dm, bb.x), 0.f));
            v.y = wmma::__float_to_tf32(fmaxf(fmaf(v.y, dm, bb.y), 0.f));
            v.z = wmma::__float_to_tf32(fmaxf(fmaf(v.z, dm, bb.z), 0.f));
            v.w = wmma::__float_to_tf32(fmaxf(fmaf(v.w, dm, bb.w), 0.f));
            *(float4*)&S[m * LDS_T + c] = v;
        }
    }
    __syncthreads();

    // ---- stage2: O = H @ Wc (128x16 result), each warp 16 rows ----
    {
        wmma::fragment<wmma::accumulator, 16, 16, 8, float> acc2;
        wmma::fill_fragment(acc2, 0.f);
        #pragma unroll
        for (int k0 = 0; k0 < 128; k0 += 8) {
            wmma::fragment<wmma::matrix_a, 16, 16, 8, wmma::precision::tf32,
                           wmma::row_major> af2;
            wmma::load_matrix_sync(af2, S + mrow2 * LDS_T + k0, LDS_T);
            wmma::fragment<wmma::matrix_b, 16, 16, 8, wmma::precision::tf32,
                           wmma::row_major> bf2;
            wmma::load_matrix_sync(bf2, Wcs + k0 * 16, 16);
            wmma::mma_sync(acc2, af2, bf2, acc2);
        }
        wmma::store_matrix_sync(O + mrow2 * 16, acc2, 16, wmma::mem_row_major);
    }
    __syncthreads();

    // global write/accumulate: 2048 floats, 8 per thread
    {
        int m  = tid >> 1;
        int c0 = (tid & 1) * 8;
        int node = m0 + m;
        if (node < N_NODES) {
            float4 v0 = *(const float4*)&O[m * 16 + c0];
            float4 v1 = *(const float4*)&O[m * 16 + c0 + 4];
            float* dst = &out[node * 16 + c0];
            if (FIRST) {
                float4 bc0 = *(const float4*)&bc[c0];
                float4 bc1 = *(const float4*)&bc[c0 + 4];
                v0.x += bc0.x; v0.y += bc0.y; v0.z += bc0.z; v0.w += bc0.w;
                v1.x += bc1.x; v1.y += bc1.y; v1.z += bc1.z; v1.w += bc1.w;
                *(float4*)&dst[0] = v0;
                *(float4*)&dst[4] = v1;
            } else {
                float4 o0 = *(const float4*)&dst[0];
                float4 o1 = *(const float4*)&dst[4];
                o0.x += v0.x; o0.y += v0.y; o0.z += v0.z; o0.w += v0.w;
                o1.x += v1.x; o1.y += v1.y; o1.z += v1.z; o1.w += v1.w;
                *(float4*)&dst[0] = o0;
                *(float4*)&dst[4] = o1;
            }
        }
    }
}

__global__ __launch_bounds__(256, 2)
void k_mlp_ego(const float* __restrict__ x,
               const float* __restrict__ W, const float* __restrict__ b,
               const float* __restrict__ Wc, const float* __restrict__ bc,
               float* __restrict__ out) {
    extern __shared__ char smem_raw[];
    mlp_tile<0, true>(blockIdx.x * 128, x, W, b, Wc, bc, out, smem_raw);
}

__global__ __launch_bounds__(256, 2)
void k_mlp_b1(const float* __restrict__ y1f,
              const float* __restrict__ W, const float* __restrict__ b,
              const float* __restrict__ Wc, float* __restrict__ out) {
    extern __shared__ char smem_raw[];
    mlp_tile<1, false>(blockIdx.x * 128, y1f, W, b, Wc + 2048, nullptr, out, smem_raw);
}

__global__ __launch_bounds__(256, 2)
void k_mlp_b2(const float* __restrict__ y2f,
              const float* __restrict__ W, const float* __restrict__ b,
              const float* __restrict__ Wc, float* __restrict__ out) {
    extern __shared__ char smem_raw[];
    mlp_tile<2, false>(blockIdx.x * 128, y2f, W, b, Wc + 4096, nullptr, out, smem_raw);
}

// ---------------- launch: fork/join multi-stream for overlap ----------------
// NOTE: ego stays the 4th host-side launch so ncu keeps profiling the MLP.
extern "C" void kernel_launch(void* const* d_in, const int* in_sizes, int n_in,
                              void* d_out, int out_size) {
    const float* x    = (const float*)d_in[0];
    const int*   ei   = (const int*)d_in[1];
    const float* Wego = (const float*)d_in[2];
    const float* bego = (const float*)d_in[3];
    const float* W1   = (const float*)d_in[4];
    const float* b1   = (const float*)d_in[5];
    const float* W2   = (const float*)d_in[6];
    const float* b2   = (const float*)d_in[7];
    const float* Wc   = (const float*)d_in[8];
    const float* bc   = (const float*)d_in[9];
    float*       out  = (float*)d_out;

    void *py1 = nullptr, *py2 = nullptr;
    cudaGetSymbolAddress(&py1, g_y1);
    cudaGetSymbolAddress(&py2, g_y2);

    cudaFuncSetAttribute(k_mlp_ego, cudaFuncAttributeMaxDynamicSharedMemorySize, SM_TOTAL);
    cudaFuncSetAttribute(k_mlp_b1,  cudaFuncAttributeMaxDynamicSharedMemorySize, SM_TOTAL);
    cudaFuncSetAttribute(k_mlp_b2,  cudaFuncAttributeMaxDynamicSharedMemorySize, SM_TOTAL);

    cudaStream_t sB;
    cudaStreamCreateWithFlags(&sB, cudaStreamNonBlocking);
    cudaEvent_t eFork, eS1, eS2, eJoin;
    cudaEventCreateWithFlags(&eFork, cudaEventDisableTiming);
    cudaEventCreateWithFlags(&eS1,   cudaEventDisableTiming);
    cudaEventCreateWithFlags(&eS2,   cudaEventDisableTiming);
    cudaEventCreateWithFlags(&eJoin, cudaEventDisableTiming);

    // stream 0: CSR build head (launches 1-3)
    k_zero<<<(N_NODES + 1023) / 1024, 1024>>>(ei);
    k_count<<<(N_EDGES + 255) / 256, 256>>>(ei);
    k_alloc<<<(N_NODES + 255) / 256, 256>>>();

    // fork + ego as the 4th launch (profiled)
    cudaEventRecord(eFork, 0);
    cudaStreamWaitEvent(sB, eFork, 0);
    k_mlp_ego<<<MLP_CTAS, 256, SM_TOTAL, sB>>>(x, Wego, bego, Wc, bc, out);

    // stream 0: rest of CSR + spmm chain
    k_scatter<<<(N_EDGES + 255) / 256, 256>>>(ei);
    dim3 sb(32, 4);
    k_spmm<<<(N_NODES + 3) / 4, sb>>>((const float4*)x, (float4*)py1);
    cudaEventRecord(eS1, 0);
    k_spmm<<<(N_NODES + 3) / 4, sb>>>((const float4*)py1, (float4*)py2);
    cudaEventRecord(eS2, 0);

    // stream B: branch 1 after spmm1 (overlaps spmm2), branch 2 after spmm2
    cudaStreamWaitEvent(sB, eS1, 0);
    k_mlp_b1<<<MLP_CTAS, 256, SM_TOTAL, sB>>>((const float*)py1, W1, b1, Wc, out);
    cudaStreamWaitEvent(sB, eS2, 0);
    k_mlp_b2<<<MLP_CTAS, 256, SM_TOTAL, sB>>>((const float*)py2, W2, b2, Wc, out);

    cudaEventRecord(eJoin, sB);
    cudaStreamWaitEvent(0, eJoin, 0);

    cudaEventDestroy(eFork);
    cudaEventDestroy(eS1);
    cudaEventDestroy(eS2);
    cudaEventDestroy(eJoin);
}